// round 3
// baseline (speedup 1.0000x reference)
#include <cuda_runtime.h>
#include <math.h>

#define N_CRIT   128
#define N_PAIRS  8128          // 128*127/2
#define N_TOT    8256          // N_CRIT + N_PAIRS
#define N_VEC4   2064          // N_TOT / 4
#define BATCH    16384
#define MIN_W    1e-7f
#define ROWS_PER_BLOCK 8

__device__ float g_w[N_TOT];       // constrained weights (wc_eff ‖ wint_eff)
__device__ float g_params[2];      // [0] = 1/weight_sum, [1] = thr

// ---------------------------------------------------------------------------
// Prep: build constrained weights + weight sum. Single block, 256 threads.
// ---------------------------------------------------------------------------
__global__ void prep_weights_kernel(const float* __restrict__ wc,
                                    const float* __restrict__ wint,
                                    const float* __restrict__ thr) {
    __shared__ float s_wc[N_CRIT];
    __shared__ float s_red[256];

    const int tid = threadIdx.x;
    float local = 0.0f;

    if (tid < N_CRIT) {
        float w = wc[tid];
        w = (w < 0.0f) ? MIN_W : w;
        s_wc[tid] = w;
        g_w[tid]  = w;
        local += w;
    }
    __syncthreads();

    // pairs (i,j), i<j, row-major upper triangle; start(i) = i*(255-i)/2
    for (int p = tid; p < N_PAIRS; p += 256) {
        float fi = (255.0f - sqrtf(255.0f * 255.0f - 8.0f * (float)p)) * 0.5f;
        int i = (int)fi;
        if (i > 126) i = 126;
        if (i < 0) i = 0;
        while (i * (255 - i) / 2 > p) --i;
        while ((i + 1) * (254 - i) / 2 <= p) ++i;
        int j = p - i * (255 - i) / 2 + i + 1;

        float lower = fmaxf(-s_wc[i], -s_wc[j]);
        float w = fmaxf(wint[p], lower);
        g_w[N_CRIT + p] = w;
        local += w;
    }

    // block reduce sum
    s_red[tid] = local;
    __syncthreads();
    for (int off = 128; off > 0; off >>= 1) {
        if (tid < off) s_red[tid] += s_red[tid + off];
        __syncthreads();
    }
    if (tid == 0) {
        g_params[0] = 1.0f / s_red[0];
        g_params[1] = thr[0];
    }
}

// ---------------------------------------------------------------------------
// Main: warp-per-row GEMV with weights staged in shared memory.
// grid = BATCH / ROWS_PER_BLOCK blocks, 256 threads (8 warps).
// ---------------------------------------------------------------------------
__global__ __launch_bounds__(256)
void choquet_gemv_kernel(const float* __restrict__ x,
                         float* __restrict__ out) {
    __shared__ float4 s_w[N_VEC4];   // 33 KB

    const int tid = threadIdx.x;

    // stage weights into smem (coalesced float4)
    const float4* gw4 = reinterpret_cast<const float4*>(g_w);
    #pragma unroll
    for (int k = tid; k < N_VEC4; k += 256) {
        s_w[k] = gw4[k];
    }
    __syncthreads();

    const int warp = tid >> 5;
    const int lane = tid & 31;
    const int row  = blockIdx.x * ROWS_PER_BLOCK + warp;

    const float4* xr = reinterpret_cast<const float4*>(x + (size_t)row * N_TOT);

    float acc = 0.0f;
    int k = lane;
    // 2064 float4 / 32 lanes = 64 full iterations + tail of 16
    #pragma unroll 8
    for (int it = 0; it < 64; ++it, k += 32) {
        float4 a = xr[k];
        float4 b = s_w[k];
        acc = fmaf(a.x, b.x, acc);
        acc = fmaf(a.y, b.y, acc);
        acc = fmaf(a.z, b.z, acc);
        acc = fmaf(a.w, b.w, acc);
    }
    if (k < N_VEC4) {   // lanes 0..15
        float4 a = xr[k];
        float4 b = s_w[k];
        acc = fmaf(a.x, b.x, acc);
        acc = fmaf(a.y, b.y, acc);
        acc = fmaf(a.z, b.z, acc);
        acc = fmaf(a.w, b.w, acc);
    }

    // warp reduce
    #pragma unroll
    for (int off = 16; off > 0; off >>= 1) {
        acc += __shfl_xor_sync(0xFFFFFFFFu, acc, off);
    }

    if (lane == 0) {
        float score = acc * g_params[0] - g_params[1];
        out[row] = 1.0f / (1.0f + expf(-score));
    }
}

// ---------------------------------------------------------------------------
extern "C" void kernel_launch(void* const* d_in, const int* in_sizes, int n_in,
                              void* d_out, int out_size) {
    const float* x    = (const float*)d_in[0];
    const float* wc   = (const float*)d_in[1];
    const float* wint = (const float*)d_in[2];
    const float* thr  = (const float*)d_in[3];
    float* out = (float*)d_out;

    prep_weights_kernel<<<1, 256>>>(wc, wint, thr);
    choquet_gemv_kernel<<<BATCH / ROWS_PER_BLOCK, 256>>>(x, out);
}

// round 4
// speedup vs baseline: 1.1580x; 1.1580x over previous
#include <cuda_runtime.h>
#include <math.h>

#define N_CRIT   128
#define N_PAIRS  8128          // 128*127/2
#define N_TOT    8256          // N_CRIT + N_PAIRS
#define N_VEC4   2064          // N_TOT / 4
#define BATCH    16384
#define MIN_W    1e-7f
#define ROWS_PER_BLOCK 8

// ---------------------------------------------------------------------------
// Fused kernel: each block builds the constrained weight vector + 1/sum in
// shared memory, then its 8 warps each stream one row of x (warp-per-row).
// grid = BATCH / ROWS_PER_BLOCK blocks, 256 threads.
// ---------------------------------------------------------------------------
__global__ __launch_bounds__(256)
void choquet_fused_kernel(const float* __restrict__ x,
                          const float* __restrict__ wc,
                          const float* __restrict__ wint,
                          const float* __restrict__ thr,
                          float* __restrict__ out) {
    __shared__ __align__(16) float s_w[N_TOT];   // 33 KB constrained weights
    __shared__ float s_red[256];
    __shared__ float s_inv, s_thr;

    const int tid = threadIdx.x;
    float local = 0.0f;

    // --- wc_eff: clamp negatives to MIN_W ---
    if (tid < N_CRIT) {
        float w = wc[tid];
        w = (w < 0.0f) ? MIN_W : w;
        s_w[tid] = w;
        local += w;
    }
    __syncthreads();   // s_w[0..127] visible for pair decode below

    // --- wint_eff: w_ij = max(wint[p], -wc_i, -wc_j), row-major upper tri ---
    for (int p = tid; p < N_PAIRS; p += 256) {
        // invert start(i) = i*(255-i)/2  via sqrt + integer fixup
        float fi = (255.0f - sqrtf(65025.0f - 8.0f * (float)p)) * 0.5f;
        int i = (int)fi;
        if (i > 126) i = 126;
        if (i < 0) i = 0;
        while (i * (255 - i) / 2 > p) --i;
        while ((i + 1) * (254 - i) / 2 <= p) ++i;
        int j = p - i * (255 - i) / 2 + i + 1;

        float lower = fmaxf(-s_w[i], -s_w[j]);
        float w = fmaxf(wint[p], lower);
        s_w[N_CRIT + p] = w;
        local += w;
    }

    // --- block-reduce weight sum ---
    s_red[tid] = local;
    __syncthreads();
    #pragma unroll
    for (int off = 128; off > 0; off >>= 1) {
        if (tid < off) s_red[tid] += s_red[tid + off];
        __syncthreads();
    }
    if (tid == 0) {
        s_inv = 1.0f / s_red[0];
        s_thr = thr[0];
    }
    __syncthreads();   // weights + params ready

    // --- warp-per-row GEMV ---
    const int warp = tid >> 5;
    const int lane = tid & 31;
    const int row  = blockIdx.x * ROWS_PER_BLOCK + warp;

    const float4* xr  = reinterpret_cast<const float4*>(x + (size_t)row * N_TOT);
    const float4* sw4 = reinterpret_cast<const float4*>(s_w);

    float acc = 0.0f;
    int k = lane;
    // 2064 float4 / 32 lanes = 64 full iterations + tail of 16
    #pragma unroll 8
    for (int it = 0; it < 64; ++it, k += 32) {
        float4 a = __ldcs(&xr[k]);        // streaming: read-once, evict-first
        float4 b = sw4[k];
        acc = fmaf(a.x, b.x, acc);
        acc = fmaf(a.y, b.y, acc);
        acc = fmaf(a.z, b.z, acc);
        acc = fmaf(a.w, b.w, acc);
    }
    if (k < N_VEC4) {   // lanes 0..15
        float4 a = __ldcs(&xr[k]);
        float4 b = sw4[k];
        acc = fmaf(a.x, b.x, acc);
        acc = fmaf(a.y, b.y, acc);
        acc = fmaf(a.z, b.z, acc);
        acc = fmaf(a.w, b.w, acc);
    }

    // warp reduce
    #pragma unroll
    for (int off = 16; off > 0; off >>= 1) {
        acc += __shfl_xor_sync(0xFFFFFFFFu, acc, off);
    }

    if (lane == 0) {
        float score = acc * s_inv - s_thr;
        out[row] = 1.0f / (1.0f + expf(-score));
    }
}

// ---------------------------------------------------------------------------
extern "C" void kernel_launch(void* const* d_in, const int* in_sizes, int n_in,
                              void* d_out, int out_size) {
    const float* x    = (const float*)d_in[0];
    const float* wc   = (const float*)d_in[1];
    const float* wint = (const float*)d_in[2];
    const float* thr  = (const float*)d_in[3];
    float* out = (float*)d_out;

    choquet_fused_kernel<<<BATCH / ROWS_PER_BLOCK, 256>>>(x, wc, wint, thr, out);
}

// round 6
// speedup vs baseline: 1.4026x; 1.2113x over previous
#include <cuda_runtime.h>
#include <math.h>

#define N_CRIT   128
#define N_PAIRS  8128          // 128*127/2
#define N_TOT    8256          // N_CRIT + N_PAIRS
#define N_VEC4   2064          // N_TOT / 4
#define BATCH    16384
#define MIN_W    1e-7f
#define THREADS  512
#define ROWS_PER_BLOCK 16      // 16 warps, one row each

__device__ float g_w[N_TOT];   // constrained weights (wc_eff ‖ wint_eff)

// ---------------------------------------------------------------------------
// Prep: one pair per thread. grid = 32 blocks x 256 threads (8192 >= 8128).
// ---------------------------------------------------------------------------
__global__ __launch_bounds__(256)
void prep_weights_kernel(const float* __restrict__ wc,
                         const float* __restrict__ wint) {
    __shared__ float s_wc[N_CRIT];

    const int tid = threadIdx.x;
    if (tid < N_CRIT) {
        float w = wc[tid];
        w = (w < 0.0f) ? MIN_W : w;
        s_wc[tid] = w;
        if (blockIdx.x == 0) g_w[tid] = w;
    }
    __syncthreads();

    const int p = blockIdx.x * 256 + tid;
    if (p < N_PAIRS) {
        // invert start(i) = i*(255-i)/2 via sqrt + integer fixup (<=1 step)
        float fi = (255.0f - sqrtf(65025.0f - 8.0f * (float)p)) * 0.5f;
        int i = (int)fi;
        if (i > 126) i = 126;
        if (i < 0) i = 0;
        while (i * (255 - i) / 2 > p) --i;
        while ((i + 1) * (254 - i) / 2 <= p) ++i;
        int j = p - i * (255 - i) / 2 + i + 1;

        float lower = fmaxf(-s_wc[i], -s_wc[j]);
        g_w[N_CRIT + p] = fmaxf(wint[p], lower);
    }
}

// ---------------------------------------------------------------------------
// GEMV: 512 threads (16 warps), warp-per-row, weights staged in smem.
// __launch_bounds__(512, 4) forces regs <= 32 -> 64 warps/SM (full occ).
// grid = BATCH / 16 = 1024 blocks.
// ---------------------------------------------------------------------------
__global__ __launch_bounds__(THREADS, 4)
void choquet_gemv_kernel(const float* __restrict__ x,
                         const float* __restrict__ thr,
                         float* __restrict__ out) {
    __shared__ __align__(16) float s_w[N_TOT];   // 33 KB
    __shared__ float s_red[THREADS];
    __shared__ float s_inv;

    const int tid = threadIdx.x;

    // stage weights (coalesced float4) and accumulate partial sum
    const float4* gw4 = reinterpret_cast<const float4*>(g_w);
    float4* sw4 = reinterpret_cast<float4*>(s_w);
    float wsum = 0.0f;
    for (int k = tid; k < N_VEC4; k += THREADS) {
        float4 v = gw4[k];
        sw4[k] = v;
        wsum += v.x + v.y + v.z + v.w;
    }

    // block reduce the weight sum
    s_red[tid] = wsum;
    __syncthreads();
    #pragma unroll
    for (int off = THREADS / 2; off > 0; off >>= 1) {
        if (tid < off) s_red[tid] += s_red[tid + off];
        __syncthreads();
    }
    if (tid == 0) s_inv = 1.0f / s_red[0];
    __syncthreads();

    const int warp = tid >> 5;
    const int lane = tid & 31;
    const int row  = blockIdx.x * ROWS_PER_BLOCK + warp;

    const float4* xr = reinterpret_cast<const float4*>(x + (size_t)row * N_TOT);

    float acc = 0.0f;
    int k = lane;
    // 2064 float4 / 32 lanes = 64 full iterations + tail of 16
    #pragma unroll 4
    for (int it = 0; it < 64; ++it, k += 32) {
        float4 a = __ldcs(&xr[k]);       // streaming: read-once
        float4 b = sw4[k];
        acc = fmaf(a.x, b.x, acc);
        acc = fmaf(a.y, b.y, acc);
        acc = fmaf(a.z, b.z, acc);
        acc = fmaf(a.w, b.w, acc);
    }
    if (k < N_VEC4) {   // lanes 0..15
        float4 a = __ldcs(&xr[k]);
        float4 b = sw4[k];
        acc = fmaf(a.x, b.x, acc);
        acc = fmaf(a.y, b.y, acc);
        acc = fmaf(a.z, b.z, acc);
        acc = fmaf(a.w, b.w, acc);
    }

    // warp reduce
    #pragma unroll
    for (int off = 16; off > 0; off >>= 1) {
        acc += __shfl_xor_sync(0xFFFFFFFFu, acc, off);
    }

    if (lane == 0) {
        float score = acc * s_inv - thr[0];
        out[row] = 1.0f / (1.0f + expf(-score));
    }
}

// ---------------------------------------------------------------------------
extern "C" void kernel_launch(void* const* d_in, const int* in_sizes, int n_in,
                              void* d_out, int out_size) {
    const float* x    = (const float*)d_in[0];
    const float* wc   = (const float*)d_in[1];
    const float* wint = (const float*)d_in[2];
    const float* thr  = (const float*)d_in[3];
    float* out = (float*)d_out;

    prep_weights_kernel<<<32, 256>>>(wc, wint);
    choquet_gemv_kernel<<<BATCH / ROWS_PER_BLOCK, THREADS>>>(x, thr, out);
}